// round 1
// baseline (speedup 1.0000x reference)
#include <cuda_runtime.h>
#include <math.h>

#define BB 8
#define TT 2048
#define DD 1024
#define EE 1024

// -------- scratch (device globals; allocation-free) --------
__device__ float g_Q[(size_t)BB * TT * EE];          // 64 MB
__device__ float g_K[(size_t)BB * TT * EE];          // 64 MB
__device__ float g_V[(size_t)BB * TT * EE];          // 64 MB
__device__ float g_S[(size_t)BB * TT * TT];          // 134 MB (scores, then exp(scores-m))
__device__ unsigned g_max_u[BB];
__device__ float g_psum[BB * 2048];
__device__ float g_inv_sum[BB];

// monotone float<->uint mapping (order-preserving) for atomicMax
__device__ __forceinline__ unsigned f2mono(float f) {
    unsigned u = __float_as_uint(f);
    return (u & 0x80000000u) ? ~u : (u | 0x80000000u);
}
__device__ __forceinline__ float mono2f(unsigned v) {
    return (v & 0x80000000u) ? __uint_as_float(v ^ 0x80000000u)
                             : __uint_as_float(~v);
}

__global__ void init_kernel() {
    if (threadIdx.x < BB) g_max_u[threadIdx.x] = 0u;  // maps below every real float
}

// ---------------------------------------------------------------------------
// Projection: C[M=16384, 1024] = A[M,1024] @ W[1024,1024] + bias
// sel: 0->g_Q, 1->g_K, 2->g_V
// ---------------------------------------------------------------------------
__global__ __launch_bounds__(256) void proj_kernel(
    const float* __restrict__ A, const float* __restrict__ W,
    const float* __restrict__ bias, int sel)
{
    __shared__ float As[16][68];  // transposed A tile, padded
    __shared__ float Bs[16][64];  // natural W tile

    float* __restrict__ C = (sel == 0) ? g_Q : (sel == 1) ? g_K : g_V;

    const int tid = threadIdx.x;
    const int tx = tid & 15, ty = tid >> 4;
    const int m0 = blockIdx.y * 64, n0 = blockIdx.x * 64;

    float acc[4][4] = {};

    for (int k0 = 0; k0 < DD; k0 += 16) {
#pragma unroll
        for (int it = 0; it < 4; ++it) {
            int idx = tid + it * 256;
            int ml = idx >> 4, kl = idx & 15;
            As[kl][ml] = A[(size_t)(m0 + ml) * DD + k0 + kl];
        }
#pragma unroll
        for (int it = 0; it < 4; ++it) {
            int idx = tid + it * 256;
            int kl = idx >> 6, nl = idx & 63;
            Bs[kl][nl] = W[(size_t)(k0 + kl) * EE + n0 + nl];
        }
        __syncthreads();
#pragma unroll
        for (int dk = 0; dk < 16; ++dk) {
            float4 a4 = *reinterpret_cast<const float4*>(&As[dk][ty * 4]);
            float4 b4 = *reinterpret_cast<const float4*>(&Bs[dk][tx * 4]);
            float av[4] = {a4.x, a4.y, a4.z, a4.w};
            float bv[4] = {b4.x, b4.y, b4.z, b4.w};
#pragma unroll
            for (int i = 0; i < 4; ++i)
#pragma unroll
                for (int j = 0; j < 4; ++j) acc[i][j] += av[i] * bv[j];
        }
        __syncthreads();
    }
#pragma unroll
    for (int i = 0; i < 4; ++i) {
        int m = m0 + ty * 4 + i;
#pragma unroll
        for (int j = 0; j < 4; ++j) {
            int n = n0 + tx * 4 + j;
            C[(size_t)m * EE + n] = acc[i][j] + bias[n];
        }
    }
}

// ---------------------------------------------------------------------------
// Scores: S[b,t,s] = (Q[b,t,:] . K[b,s,:]) / 32 if s<=t else -1e30
// Also atomicMax of causal entries into g_max_u[b].
// ---------------------------------------------------------------------------
__global__ __launch_bounds__(256) void scores_kernel()
{
    const int bz = blockIdx.z;
    const int t0 = blockIdx.y * 64, s0 = blockIdx.x * 64;
    const int tid = threadIdx.x;
    const int tx = tid & 15, ty = tid >> 4;

    float* __restrict__ S = g_S + (size_t)bz * TT * TT;

    if (s0 > t0 + 63) {  // fully masked block: no GEMM
#pragma unroll
        for (int i = 0; i < 4; ++i) {
            int t = t0 + ty * 4 + i;
#pragma unroll
            for (int j = 0; j < 4; ++j)
                S[(size_t)t * TT + s0 + tx * 4 + j] = -1e30f;
        }
        return;
    }

    const float* __restrict__ Q = g_Q + (size_t)bz * TT * EE;
    const float* __restrict__ K = g_K + (size_t)bz * TT * EE;

    __shared__ float As[16][68];
    __shared__ float Bs[16][68];

    float acc[4][4] = {};

    for (int k0 = 0; k0 < EE; k0 += 16) {
#pragma unroll
        for (int it = 0; it < 4; ++it) {
            int idx = tid + it * 256;
            int tl = idx >> 4, kl = idx & 15;
            As[kl][tl] = Q[(size_t)(t0 + tl) * EE + k0 + kl];
        }
#pragma unroll
        for (int it = 0; it < 4; ++it) {
            int idx = tid + it * 256;
            int sl = idx >> 4, kl = idx & 15;
            Bs[kl][sl] = K[(size_t)(s0 + sl) * EE + k0 + kl];
        }
        __syncthreads();
#pragma unroll
        for (int dk = 0; dk < 16; ++dk) {
            float4 a4 = *reinterpret_cast<const float4*>(&As[dk][ty * 4]);
            float4 b4 = *reinterpret_cast<const float4*>(&Bs[dk][tx * 4]);
            float av[4] = {a4.x, a4.y, a4.z, a4.w};
            float bv[4] = {b4.x, b4.y, b4.z, b4.w};
#pragma unroll
            for (int i = 0; i < 4; ++i)
#pragma unroll
                for (int j = 0; j < 4; ++j) acc[i][j] += av[i] * bv[j];
        }
        __syncthreads();
    }

    float lmax = -3.4e38f;
#pragma unroll
    for (int i = 0; i < 4; ++i) {
        int t = t0 + ty * 4 + i;
#pragma unroll
        for (int j = 0; j < 4; ++j) {
            int s = s0 + tx * 4 + j;
            float v;
            if (s <= t) {
                v = acc[i][j] * 0.03125f;  // 1/sqrt(1024)
                lmax = fmaxf(lmax, v);
            } else {
                v = -1e30f;
            }
            S[(size_t)t * TT + s] = v;
        }
    }

    __shared__ float red[256];
    red[tid] = lmax;
    __syncthreads();
    for (int st = 128; st > 0; st >>= 1) {
        if (tid < st) red[tid] = fmaxf(red[tid], red[tid + st]);
        __syncthreads();
    }
    if (tid == 0) atomicMax(&g_max_u[bz], f2mono(red[0]));
}

// ---------------------------------------------------------------------------
// exp(S - m) in place + deterministic per-chunk partial sums.
// grid = (2048 chunks, B). 2048 floats per chunk.
// ---------------------------------------------------------------------------
__global__ __launch_bounds__(256) void exp_kernel()
{
    const int bz = blockIdx.y;
    const float m = mono2f(g_max_u[bz]);
    float4* p = reinterpret_cast<float4*>(
        g_S + (size_t)bz * TT * TT + (size_t)blockIdx.x * 2048);

    float lsum = 0.0f;
#pragma unroll
    for (int it = 0; it < 2; ++it) {
        float4 v = p[threadIdx.x + it * 256];
        v.x = expf(v.x - m);
        v.y = expf(v.y - m);
        v.z = expf(v.z - m);
        v.w = expf(v.w - m);
        p[threadIdx.x + it * 256] = v;
        lsum += (v.x + v.y) + (v.z + v.w);
    }

    __shared__ float red[256];
    red[threadIdx.x] = lsum;
    __syncthreads();
    for (int st = 128; st > 0; st >>= 1) {
        if (threadIdx.x < st) red[threadIdx.x] += red[threadIdx.x + st];
        __syncthreads();
    }
    if (threadIdx.x == 0) g_psum[bz * 2048 + blockIdx.x] = red[0];
}

// deterministic final reduce: grid = B blocks
__global__ __launch_bounds__(256) void reduce_kernel()
{
    const int bz = blockIdx.x;
    float s = 0.0f;
    for (int i = threadIdx.x; i < 2048; i += 256) s += g_psum[bz * 2048 + i];
    __shared__ float red[256];
    red[threadIdx.x] = s;
    __syncthreads();
    for (int st = 128; st > 0; st >>= 1) {
        if (threadIdx.x < st) red[threadIdx.x] += red[threadIdx.x + st];
        __syncthreads();
    }
    if (threadIdx.x == 0) g_inv_sum[bz] = 1.0f / red[0];
}

// ---------------------------------------------------------------------------
// Output: O[b,t,:] = (E[b,t,:] @ V[b]) * inv_sum[b]; k-loop truncated at diag.
// ---------------------------------------------------------------------------
__global__ __launch_bounds__(256) void out_kernel(float* __restrict__ O)
{
    const int bz = blockIdx.z;
    const int t0 = blockIdx.y * 64, n0 = blockIdx.x * 64;
    const int tid = threadIdx.x;
    const int tx = tid & 15, ty = tid >> 4;

    const float* __restrict__ Eb = g_S + (size_t)bz * TT * TT;
    const float* __restrict__ V  = g_V + (size_t)bz * TT * EE;
    const float inv = g_inv_sum[bz];

    __shared__ float As[16][68];
    __shared__ float Bs[16][64];

    float acc[4][4] = {};

    const int kend = t0 + 64;  // s <= t0+63 contributes; beyond is exactly 0
    for (int k0 = 0; k0 < kend; k0 += 16) {
#pragma unroll
        for (int it = 0; it < 4; ++it) {
            int idx = tid + it * 256;
            int tl = idx >> 4, kl = idx & 15;
            As[kl][tl] = Eb[(size_t)(t0 + tl) * TT + k0 + kl];
        }
#pragma unroll
        for (int it = 0; it < 4; ++it) {
            int idx = tid + it * 256;
            int kl = idx >> 6, nl = idx & 63;
            Bs[kl][nl] = V[(size_t)(k0 + kl) * EE + n0 + nl];
        }
        __syncthreads();
#pragma unroll
        for (int dk = 0; dk < 16; ++dk) {
            float4 a4 = *reinterpret_cast<const float4*>(&As[dk][ty * 4]);
            float4 b4 = *reinterpret_cast<const float4*>(&Bs[dk][tx * 4]);
            float av[4] = {a4.x, a4.y, a4.z, a4.w};
            float bv[4] = {b4.x, b4.y, b4.z, b4.w};
#pragma unroll
            for (int i = 0; i < 4; ++i)
#pragma unroll
                for (int j = 0; j < 4; ++j) acc[i][j] += av[i] * bv[j];
        }
        __syncthreads();
    }

#pragma unroll
    for (int i = 0; i < 4; ++i) {
        int t = t0 + ty * 4 + i;
#pragma unroll
        for (int j = 0; j < 4; ++j) {
            int n = n0 + tx * 4 + j;
            O[((size_t)bz * TT + t) * EE + n] = acc[i][j] * inv;
        }
    }
}

// ---------------------------------------------------------------------------
extern "C" void kernel_launch(void* const* d_in, const int* in_sizes, int n_in,
                              void* d_out, int out_size)
{
    const float* x  = (const float*)d_in[0];
    const float* Wq = (const float*)d_in[1];
    const float* bq = (const float*)d_in[2];
    const float* Wk = (const float*)d_in[3];
    const float* bk = (const float*)d_in[4];
    const float* Wv = (const float*)d_in[5];
    const float* bv = (const float*)d_in[6];
    float* out = (float*)d_out;

    init_kernel<<<1, 32>>>();

    dim3 pgrid(EE / 64, (BB * TT) / 64);           // 16 x 256
    proj_kernel<<<pgrid, 256>>>(x, Wq, bq, 0);
    proj_kernel<<<pgrid, 256>>>(x, Wk, bk, 1);
    proj_kernel<<<pgrid, 256>>>(x, Wv, bv, 2);

    dim3 sgrid(TT / 64, TT / 64, BB);              // 32 x 32 x 8
    scores_kernel<<<sgrid, 256>>>();

    exp_kernel<<<dim3(2048, BB), 256>>>();
    reduce_kernel<<<BB, 256>>>();

    dim3 ogrid(EE / 64, TT / 64, BB);              // 16 x 32 x 8
    out_kernel<<<ogrid, 256>>>(out);
}

// round 2
// speedup vs baseline: 2.9553x; 2.9553x over previous
#include <cuda_runtime.h>
#include <math.h>
#include <stdint.h>

#define BB 8
#define TT 2048
#define DD 1024
#define EE 1024

#define A_STRIDE 44    // 128x32 A tile, pad: conflict-free frag loads + 16B rows
#define B_STRIDE 136   // 32x128 B tile, pad: conflict-free frag loads + 16B rows

// -------- scratch (device globals; allocation-free) --------
__device__ float g_Q[(size_t)BB * TT * EE];
__device__ float g_K[(size_t)BB * TT * EE];
__device__ float g_V[(size_t)BB * TT * EE];
__device__ float g_S[(size_t)BB * TT * TT];
__device__ unsigned g_max_u[BB];
__device__ float g_psum[BB * 2048];
__device__ float g_inv_sum[BB];

__device__ __forceinline__ unsigned f2mono(float f) {
    unsigned u = __float_as_uint(f);
    return (u & 0x80000000u) ? ~u : (u | 0x80000000u);
}
__device__ __forceinline__ float mono2f(unsigned v) {
    return (v & 0x80000000u) ? __uint_as_float(v ^ 0x80000000u)
                             : __uint_as_float(~v);
}

__global__ void init_kernel() {
    if (threadIdx.x < BB) g_max_u[threadIdx.x] = 0u;
}

// -------- tf32 helpers --------
__device__ __forceinline__ unsigned f2tf(float f) {
    unsigned u;
    asm("cvt.rna.tf32.f32 %0, %1;" : "=r"(u) : "f"(f));
    return u;
}

__device__ __forceinline__ void mma8(float* c, unsigned a0, unsigned a1,
                                     unsigned a2, unsigned a3,
                                     unsigned b0, unsigned b1) {
    asm("mma.sync.aligned.m16n8k8.row.col.f32.tf32.tf32.f32 "
        "{%0,%1,%2,%3}, {%4,%5,%6,%7}, {%8,%9}, {%0,%1,%2,%3};"
        : "+f"(c[0]), "+f"(c[1]), "+f"(c[2]), "+f"(c[3])
        : "r"(a0), "r"(a1), "r"(a2), "r"(a3), "r"(b0), "r"(b1));
}

// Fill A tile (128 x 32) from row-major src (already offset to tile origin).
__device__ __forceinline__ void fillA(uint32_t* As, const float* src, int lda, int tid) {
#pragma unroll
    for (int it = 0; it < 4; ++it) {
        int vidx = tid + it * 256;
        int row = vidx >> 3;
        int kc = (vidx & 7) * 4;
        float4 v = *reinterpret_cast<const float4*>(src + (size_t)row * lda + kc);
        uint4 u = make_uint4(f2tf(v.x), f2tf(v.y), f2tf(v.z), f2tf(v.w));
        *reinterpret_cast<uint4*>(&As[row * A_STRIDE + kc]) = u;
    }
}

// Fill B tile (32 x 128) from row-major k x n src.
__device__ __forceinline__ void fillB(uint32_t* Bs, const float* src, int ldb, int tid) {
#pragma unroll
    for (int it = 0; it < 4; ++it) {
        int vidx = tid + it * 256;
        int row = vidx >> 5;
        int nc = (vidx & 31) * 4;
        float4 v = *reinterpret_cast<const float4*>(src + (size_t)row * ldb + nc);
        uint4 u = make_uint4(f2tf(v.x), f2tf(v.y), f2tf(v.z), f2tf(v.w));
        *reinterpret_cast<uint4*>(&Bs[row * B_STRIDE + nc]) = u;
    }
}

// Fill B tile (32 x 128) transposed: src element (k, n) at src[n*ldk + k].
__device__ __forceinline__ void fillBT(uint32_t* Bs, const float* src, int ldk, int tid) {
#pragma unroll
    for (int it = 0; it < 4; ++it) {
        int vidx = tid + it * 256;
        int n = vidx & 127;
        int kc = (vidx >> 7) * 4;
        float4 v = *reinterpret_cast<const float4*>(src + (size_t)n * ldk + kc);
        Bs[(kc + 0) * B_STRIDE + n] = f2tf(v.x);
        Bs[(kc + 1) * B_STRIDE + n] = f2tf(v.y);
        Bs[(kc + 2) * B_STRIDE + n] = f2tf(v.z);
        Bs[(kc + 3) * B_STRIDE + n] = f2tf(v.w);
    }
}

// One 32-deep k-tile of mma on the block tile. acc[4][4][4].
__device__ __forceinline__ void mma_tile(const uint32_t* As, const uint32_t* Bs,
                                         float acc[4][4][4], int wm, int wn,
                                         int g, int tg) {
#pragma unroll
    for (int kk = 0; kk < 32; kk += 8) {
        unsigned a[4][4];
#pragma unroll
        for (int mi = 0; mi < 4; ++mi) {
            const uint32_t* p = &As[(wm * 64 + mi * 16 + g) * A_STRIDE + kk + tg];
            a[mi][0] = p[0];
            a[mi][1] = p[8 * A_STRIDE];
            a[mi][2] = p[4];
            a[mi][3] = p[8 * A_STRIDE + 4];
        }
        unsigned b[4][2];
#pragma unroll
        for (int ni = 0; ni < 4; ++ni) {
            const uint32_t* p = &Bs[(kk + tg) * B_STRIDE + wn * 32 + ni * 8 + g];
            b[ni][0] = p[0];
            b[ni][1] = p[4 * B_STRIDE];
        }
#pragma unroll
        for (int mi = 0; mi < 4; ++mi)
#pragma unroll
            for (int ni = 0; ni < 4; ++ni)
                mma8(acc[mi][ni], a[mi][0], a[mi][1], a[mi][2], a[mi][3],
                     b[ni][0], b[ni][1]);
    }
}

// ---------------------------------------------------------------------------
// Projection: C[16384,1024] = A @ W + bias
// ---------------------------------------------------------------------------
__global__ __launch_bounds__(256, 2) void proj_kernel(
    const float* __restrict__ A, const float* __restrict__ W,
    const float* __restrict__ bias, int sel)
{
    __shared__ __align__(16) uint32_t As[128 * A_STRIDE];
    __shared__ __align__(16) uint32_t Bs[32 * B_STRIDE];

    float* __restrict__ C = (sel == 0) ? g_Q : (sel == 1) ? g_K : g_V;

    const int tid = threadIdx.x;
    const int warp = tid >> 5, lane = tid & 31;
    const int g = lane >> 2, tg = lane & 3;
    const int wm = warp >> 2, wn = warp & 3;
    const int m0 = blockIdx.y * 128, n0 = blockIdx.x * 128;

    const float* Ab = A + (size_t)m0 * DD;
    const float* Wb = W + n0;

    float acc[4][4][4] = {};

    for (int k0 = 0; k0 < DD; k0 += 32) {
        fillA(As, Ab + k0, DD, tid);
        fillB(Bs, Wb + (size_t)k0 * EE, EE, tid);
        __syncthreads();
        mma_tile(As, Bs, acc, wm, wn, g, tg);
        __syncthreads();
    }

#pragma unroll
    for (int mi = 0; mi < 4; ++mi) {
        int r0 = m0 + wm * 64 + mi * 16 + g;
#pragma unroll
        for (int ni = 0; ni < 4; ++ni) {
            int c = n0 + wn * 32 + ni * 8 + 2 * tg;
            float2 b2 = *reinterpret_cast<const float2*>(bias + c);
            float2 v0 = make_float2(acc[mi][ni][0] + b2.x, acc[mi][ni][1] + b2.y);
            float2 v1 = make_float2(acc[mi][ni][2] + b2.x, acc[mi][ni][3] + b2.y);
            *reinterpret_cast<float2*>(&C[(size_t)r0 * EE + c]) = v0;
            *reinterpret_cast<float2*>(&C[(size_t)(r0 + 8) * EE + c]) = v1;
        }
    }
}

// ---------------------------------------------------------------------------
// Scores: S = (Q @ K^T)/32 with causal mask; atomicMax of causal entries.
// ---------------------------------------------------------------------------
__global__ __launch_bounds__(256, 2) void scores_kernel()
{
    const int bz = blockIdx.z;
    const int t0 = blockIdx.y * 128, s0 = blockIdx.x * 128;
    const int tid = threadIdx.x;

    float* __restrict__ S = g_S + (size_t)bz * TT * TT;

    if (s0 > t0 + 127) {  // fully masked: no GEMM
        const float4 m4 = make_float4(-1e30f, -1e30f, -1e30f, -1e30f);
#pragma unroll
        for (int it = 0; it < 16; ++it) {
            int vidx = tid + it * 256;
            int r = vidx >> 5, c = (vidx & 31) * 4;
            *reinterpret_cast<float4*>(&S[(size_t)(t0 + r) * TT + s0 + c]) = m4;
        }
        return;
    }

    __shared__ __align__(16) uint32_t As[128 * A_STRIDE];
    __shared__ __align__(16) uint32_t Bs[32 * B_STRIDE];
    __shared__ float red[256];

    const int warp = tid >> 5, lane = tid & 31;
    const int g = lane >> 2, tg = lane & 3;
    const int wm = warp >> 2, wn = warp & 3;

    const float* Qb = g_Q + (size_t)bz * TT * EE + (size_t)t0 * EE;
    const float* Kb = g_K + (size_t)bz * TT * EE + (size_t)s0 * EE;

    float acc[4][4][4] = {};

    for (int k0 = 0; k0 < EE; k0 += 32) {
        fillA(As, Qb + k0, EE, tid);
        fillBT(Bs, Kb + k0, EE, tid);
        __syncthreads();
        mma_tile(As, Bs, acc, wm, wn, g, tg);
        __syncthreads();
    }

    float lmax = -3.4e38f;
#pragma unroll
    for (int mi = 0; mi < 4; ++mi) {
        int r0 = t0 + wm * 64 + mi * 16 + g;
#pragma unroll
        for (int ni = 0; ni < 4; ++ni) {
            int c = s0 + wn * 32 + ni * 8 + 2 * tg;
#pragma unroll
            for (int q = 0; q < 4; ++q) {
                int r = r0 + (q >> 1) * 8;
                int cc = c + (q & 1);
                float v;
                if (cc <= r) {
                    v = acc[mi][ni][q] * 0.03125f;
                    lmax = fmaxf(lmax, v);
                } else {
                    v = -1e30f;
                }
                S[(size_t)r * TT + cc] = v;
            }
        }
    }

    red[tid] = lmax;
    __syncthreads();
    for (int st = 128; st > 0; st >>= 1) {
        if (tid < st) red[tid] = fmaxf(red[tid], red[tid + st]);
        __syncthreads();
    }
    if (tid == 0) atomicMax(&g_max_u[bz], f2mono(red[0]));
}

// ---------------------------------------------------------------------------
// exp(S - m) in place + deterministic partial sums.
// ---------------------------------------------------------------------------
__global__ __launch_bounds__(256) void exp_kernel()
{
    const int bz = blockIdx.y;
    const float m = mono2f(g_max_u[bz]);
    float4* p = reinterpret_cast<float4*>(
        g_S + (size_t)bz * TT * TT + (size_t)blockIdx.x * 2048);

    float lsum = 0.0f;
#pragma unroll
    for (int it = 0; it < 2; ++it) {
        float4 v = p[threadIdx.x + it * 256];
        v.x = expf(v.x - m);
        v.y = expf(v.y - m);
        v.z = expf(v.z - m);
        v.w = expf(v.w - m);
        p[threadIdx.x + it * 256] = v;
        lsum += (v.x + v.y) + (v.z + v.w);
    }

    __shared__ float red[256];
    red[threadIdx.x] = lsum;
    __syncthreads();
    for (int st = 128; st > 0; st >>= 1) {
        if (threadIdx.x < st) red[threadIdx.x] += red[threadIdx.x + st];
        __syncthreads();
    }
    if (threadIdx.x == 0) g_psum[bz * 2048 + blockIdx.x] = red[0];
}

__global__ __launch_bounds__(256) void reduce_kernel()
{
    const int bz = blockIdx.x;
    float s = 0.0f;
    for (int i = threadIdx.x; i < 2048; i += 256) s += g_psum[bz * 2048 + i];
    __shared__ float red[256];
    red[threadIdx.x] = s;
    __syncthreads();
    for (int st = 128; st > 0; st >>= 1) {
        if (threadIdx.x < st) red[threadIdx.x] += red[threadIdx.x + st];
        __syncthreads();
    }
    if (threadIdx.x == 0) g_inv_sum[bz] = 1.0f / red[0];
}

// ---------------------------------------------------------------------------
// Output: O = (E @ V) * inv_sum; k-loop truncated at diagonal.
// ---------------------------------------------------------------------------
__global__ __launch_bounds__(256, 2) void out_kernel(float* __restrict__ O)
{
    const int bz = blockIdx.z;
    const int t0 = blockIdx.y * 128, n0 = blockIdx.x * 128;
    const int tid = threadIdx.x;
    const int warp = tid >> 5, lane = tid & 31;
    const int g = lane >> 2, tg = lane & 3;
    const int wm = warp >> 2, wn = warp & 3;

    __shared__ __align__(16) uint32_t As[128 * A_STRIDE];
    __shared__ __align__(16) uint32_t Bs[32 * B_STRIDE];

    const float* Eb = g_S + (size_t)bz * TT * TT + (size_t)t0 * TT;
    const float* Vb = g_V + (size_t)bz * TT * EE + n0;
    const float inv = g_inv_sum[bz];

    float acc[4][4][4] = {};

    const int kend = t0 + 128;
    for (int k0 = 0; k0 < kend; k0 += 32) {
        fillA(As, Eb + k0, TT, tid);
        fillB(Bs, Vb + (size_t)k0 * EE, EE, tid);
        __syncthreads();
        mma_tile(As, Bs, acc, wm, wn, g, tg);
        __syncthreads();
    }

#pragma unroll
    for (int mi = 0; mi < 4; ++mi) {
        int r0 = t0 + wm * 64 + mi * 16 + g;
#pragma unroll
        for (int ni = 0; ni < 4; ++ni) {
            int c = n0 + wn * 32 + ni * 8 + 2 * tg;
            float2 v0 = make_float2(acc[mi][ni][0] * inv, acc[mi][ni][1] * inv);
            float2 v1 = make_float2(acc[mi][ni][2] * inv, acc[mi][ni][3] * inv);
            *reinterpret_cast<float2*>(&O[((size_t)bz * TT + r0) * EE + c]) = v0;
            *reinterpret_cast<float2*>(&O[((size_t)bz * TT + r0 + 8) * EE + c]) = v1;
        }
    }
}

// ---------------------------------------------------------------------------
extern "C" void kernel_launch(void* const* d_in, const int* in_sizes, int n_in,
                              void* d_out, int out_size)
{
    const float* x  = (const float*)d_in[0];
    const float* Wq = (const float*)d_in[1];
    const float* bq = (const float*)d_in[2];
    const float* Wk = (const float*)d_in[3];
    const float* bk = (const float*)d_in[4];
    const float* Wv = (const float*)d_in[5];
    const float* bv = (const float*)d_in[6];
    float* out = (float*)d_out;

    init_kernel<<<1, 32>>>();

    dim3 pgrid(EE / 128, (BB * TT) / 128);          // 8 x 128
    proj_kernel<<<pgrid, 256>>>(x, Wq, bq, 0);
    proj_kernel<<<pgrid, 256>>>(x, Wk, bk, 1);
    proj_kernel<<<pgrid, 256>>>(x, Wv, bv, 2);

    dim3 sgrid(TT / 128, TT / 128, BB);             // 16 x 16 x 8
    scores_kernel<<<sgrid, 256>>>();

    exp_kernel<<<dim3(2048, BB), 256>>>();
    reduce_kernel<<<BB, 256>>>();

    dim3 ogrid(EE / 128, TT / 128, BB);             // 8 x 16 x 8
    out_kernel<<<ogrid, 256>>>(out);
}

// round 3
// speedup vs baseline: 3.1576x; 1.0684x over previous
#include <cuda_runtime.h>
#include <math.h>
#include <stdint.h>

#define BB 8
#define TT 2048
#define DD 1024
#define EE 1024

#define A_STRIDE 44    // 128x32 fp32 tile rows, 176B (16B-aligned), conflict-free frags
#define B_STRIDE 136   // 32x128 fp32 tile rows, 544B (16B-aligned), conflict-free frags

#define NCB 136        // causal 128x128 blocks per batch: 16*17/2

// -------- scratch (device globals; allocation-free) --------
__device__ float g_Q[(size_t)BB * TT * EE];
__device__ float g_K[(size_t)BB * TT * EE];
__device__ float g_V[(size_t)BB * TT * EE];
__device__ float g_S[(size_t)BB * TT * TT];
__device__ unsigned g_max_u[BB];
__device__ float g_psum[BB * NCB];
__device__ float g_inv_sum[BB];

__device__ __forceinline__ unsigned f2mono(float f) {
    unsigned u = __float_as_uint(f);
    return (u & 0x80000000u) ? ~u : (u | 0x80000000u);
}
__device__ __forceinline__ float mono2f(unsigned v) {
    return (v & 0x80000000u) ? __uint_as_float(v ^ 0x80000000u)
                             : __uint_as_float(~v);
}

__global__ void init_kernel() {
    if (threadIdx.x < BB) g_max_u[threadIdx.x] = 0u;
}

// -------- tf32 / mma / cp.async helpers --------
__device__ __forceinline__ unsigned f2tf(float f) {
    unsigned u;
    asm("cvt.rna.tf32.f32 %0, %1;" : "=r"(u) : "f"(f));
    return u;
}

__device__ __forceinline__ void mma8(float* c, unsigned a0, unsigned a1,
                                     unsigned a2, unsigned a3,
                                     unsigned b0, unsigned b1) {
    asm("mma.sync.aligned.m16n8k8.row.col.f32.tf32.tf32.f32 "
        "{%0,%1,%2,%3}, {%4,%5,%6,%7}, {%8,%9}, {%0,%1,%2,%3};"
        : "+f"(c[0]), "+f"(c[1]), "+f"(c[2]), "+f"(c[3])
        : "r"(a0), "r"(a1), "r"(a2), "r"(a3), "r"(b0), "r"(b1));
}

__device__ __forceinline__ void cpasync16(uint32_t dst, const float* src) {
    asm volatile("cp.async.ca.shared.global [%0], [%1], 16;"
                 :: "r"(dst), "l"(src));
}
__device__ __forceinline__ void cpcommit() {
    asm volatile("cp.async.commit_group;");
}
__device__ __forceinline__ void cpwait0() {
    asm volatile("cp.async.wait_group 0;");
}

// async fill: A-shaped tile (128 rows x 32 floats), row stride A_STRIDE
__device__ __forceinline__ void fillA_async(uint32_t dstu, const float* src,
                                            int lda, int tid) {
#pragma unroll
    for (int it = 0; it < 4; ++it) {
        int vidx = tid + it * 256;
        int row = vidx >> 3;
        int kc = (vidx & 7) * 4;
        cpasync16(dstu + (uint32_t)(row * A_STRIDE + kc) * 4u,
                  src + (size_t)row * lda + kc);
    }
}

// async fill: B-shaped tile (32 rows x 128 floats), row stride B_STRIDE
__device__ __forceinline__ void fillB_async(uint32_t dstu, const float* src,
                                            int ldb, int tid) {
#pragma unroll
    for (int it = 0; it < 4; ++it) {
        int vidx = tid + it * 256;
        int row = vidx >> 5;
        int nc = (vidx & 31) * 4;
        cpasync16(dstu + (uint32_t)(row * B_STRIDE + nc) * 4u,
                  src + (size_t)row * ldb + nc);
    }
}

// mma on one 32-deep k-tile; A fp32 [128 x 32]@A_STRIDE, B fp32 [32 x 128]@B_STRIDE
__device__ __forceinline__ void mma_tileB(const float* As, const float* Bs,
                                          float acc[4][4][4], int wm, int wn,
                                          int g, int tg) {
#pragma unroll
    for (int kk = 0; kk < 32; kk += 8) {
        unsigned a[4][4];
#pragma unroll
        for (int mi = 0; mi < 4; ++mi) {
            const float* p = &As[(wm * 64 + mi * 16 + g) * A_STRIDE + kk + tg];
            a[mi][0] = f2tf(p[0]);
            a[mi][1] = f2tf(p[8 * A_STRIDE]);
            a[mi][2] = f2tf(p[4]);
            a[mi][3] = f2tf(p[8 * A_STRIDE + 4]);
        }
        unsigned b[4][2];
#pragma unroll
        for (int ni = 0; ni < 4; ++ni) {
            const float* p = &Bs[(kk + tg) * B_STRIDE + wn * 32 + ni * 8 + g];
            b[ni][0] = f2tf(p[0]);
            b[ni][1] = f2tf(p[4 * B_STRIDE]);
        }
#pragma unroll
        for (int mi = 0; mi < 4; ++mi)
#pragma unroll
            for (int ni = 0; ni < 4; ++ni)
                mma8(acc[mi][ni], a[mi][0], a[mi][1], a[mi][2], a[mi][3],
                     b[ni][0], b[ni][1]);
    }
}

// mma with B given as K-tile in A layout (row = n, col = k): transpose folded in
__device__ __forceinline__ void mma_tileT(const float* As, const float* Ks,
                                          float acc[4][4][4], int wm, int wn,
                                          int g, int tg) {
#pragma unroll
    for (int kk = 0; kk < 32; kk += 8) {
        unsigned a[4][4];
#pragma unroll
        for (int mi = 0; mi < 4; ++mi) {
            const float* p = &As[(wm * 64 + mi * 16 + g) * A_STRIDE + kk + tg];
            a[mi][0] = f2tf(p[0]);
            a[mi][1] = f2tf(p[8 * A_STRIDE]);
            a[mi][2] = f2tf(p[4]);
            a[mi][3] = f2tf(p[8 * A_STRIDE + 4]);
        }
        unsigned b[4][2];
#pragma unroll
        for (int ni = 0; ni < 4; ++ni) {
            const float* p = &Ks[(wn * 32 + ni * 8 + g) * A_STRIDE + kk + tg];
            b[ni][0] = f2tf(p[0]);
            b[ni][1] = f2tf(p[4]);
        }
#pragma unroll
        for (int mi = 0; mi < 4; ++mi)
#pragma unroll
            for (int ni = 0; ni < 4; ++ni)
                mma8(acc[mi][ni], a[mi][0], a[mi][1], a[mi][2], a[mi][3],
                     b[ni][0], b[ni][1]);
    }
}

#define A_WORDS (128 * A_STRIDE)   // 5632
#define B_WORDS (32 * B_STRIDE)    // 4352
#define PROJ_SMEM_BYTES (2 * (A_WORDS + B_WORDS) * 4)   // 79872
#define SCORES_SMEM_BYTES (4 * A_WORDS * 4)             // 90112

// ---------------------------------------------------------------------------
// Projection: C[16384,1024] = A @ W + bias (2-stage cp.async pipeline)
// ---------------------------------------------------------------------------
__global__ __launch_bounds__(256, 2) void proj_kernel(
    const float* __restrict__ A, const float* __restrict__ W,
    const float* __restrict__ bias, int sel)
{
    extern __shared__ __align__(16) float smem[];
    float* Abuf[2] = {smem, smem + A_WORDS};
    float* Bbuf[2] = {smem + 2 * A_WORDS, smem + 2 * A_WORDS + B_WORDS};
    uint32_t su = (uint32_t)__cvta_generic_to_shared(smem);
    uint32_t Au[2] = {su, su + A_WORDS * 4};
    uint32_t Bu[2] = {su + 2 * A_WORDS * 4, su + (2 * A_WORDS + B_WORDS) * 4};

    float* __restrict__ C = (sel == 0) ? g_Q : (sel == 1) ? g_K : g_V;

    const int tid = threadIdx.x;
    const int warp = tid >> 5, lane = tid & 31;
    const int g = lane >> 2, tg = lane & 3;
    const int wm = warp >> 2, wn = warp & 3;
    const int m0 = blockIdx.y * 128, n0 = blockIdx.x * 128;

    const float* Ab = A + (size_t)m0 * DD;
    const float* Wb = W + n0;

    float acc[4][4][4] = {};

    fillA_async(Au[0], Ab, DD, tid);
    fillB_async(Bu[0], Wb, EE, tid);
    cpcommit();

    const int NK = DD / 32;
    for (int kt = 0; kt < NK; ++kt) {
        cpwait0();
        __syncthreads();
        if (kt + 1 < NK) {
            int k0 = (kt + 1) * 32;
            fillA_async(Au[(kt + 1) & 1], Ab + k0, DD, tid);
            fillB_async(Bu[(kt + 1) & 1], Wb + (size_t)k0 * EE, EE, tid);
        }
        cpcommit();
        mma_tileB(Abuf[kt & 1], Bbuf[kt & 1], acc, wm, wn, g, tg);
        __syncthreads();
    }

#pragma unroll
    for (int mi = 0; mi < 4; ++mi) {
        int r0 = m0 + wm * 64 + mi * 16 + g;
#pragma unroll
        for (int ni = 0; ni < 4; ++ni) {
            int c = n0 + wn * 32 + ni * 8 + 2 * tg;
            float2 b2 = *reinterpret_cast<const float2*>(bias + c);
            float2 v0 = make_float2(acc[mi][ni][0] + b2.x, acc[mi][ni][1] + b2.y);
            float2 v1 = make_float2(acc[mi][ni][2] + b2.x, acc[mi][ni][3] + b2.y);
            *reinterpret_cast<float2*>(&C[(size_t)r0 * EE + c]) = v0;
            *reinterpret_cast<float2*>(&C[(size_t)(r0 + 8) * EE + c]) = v1;
        }
    }
}

// ---------------------------------------------------------------------------
// Scores: S = (Q @ K^T)/32, causal blocks only; block max -> atomicMax.
// ---------------------------------------------------------------------------
__global__ __launch_bounds__(256, 2) void scores_kernel()
{
    const int bz = blockIdx.z;
    const int t0 = blockIdx.y * 128, s0 = blockIdx.x * 128;
    if (s0 > t0 + 127) return;  // fully masked: never read downstream

    extern __shared__ __align__(16) float smem[];
    float* Abuf[2] = {smem, smem + A_WORDS};
    float* Kbuf[2] = {smem + 2 * A_WORDS, smem + 3 * A_WORDS};
    uint32_t su = (uint32_t)__cvta_generic_to_shared(smem);
    uint32_t Au[2] = {su, su + A_WORDS * 4};
    uint32_t Ku[2] = {su + 2 * A_WORDS * 4, su + 3 * A_WORDS * 4};

    const int tid = threadIdx.x;
    const int warp = tid >> 5, lane = tid & 31;
    const int g = lane >> 2, tg = lane & 3;
    const int wm = warp >> 2, wn = warp & 3;

    float* __restrict__ S = g_S + (size_t)bz * TT * TT;
    const float* Qb = g_Q + (size_t)bz * TT * EE + (size_t)t0 * EE;
    const float* Kb = g_K + (size_t)bz * TT * EE + (size_t)s0 * EE;

    float acc[4][4][4] = {};

    fillA_async(Au[0], Qb, EE, tid);
    fillA_async(Ku[0], Kb, EE, tid);
    cpcommit();

    const int NK = EE / 32;
    for (int kt = 0; kt < NK; ++kt) {
        cpwait0();
        __syncthreads();
        if (kt + 1 < NK) {
            int k0 = (kt + 1) * 32;
            fillA_async(Au[(kt + 1) & 1], Qb + k0, EE, tid);
            fillA_async(Ku[(kt + 1) & 1], Kb + k0, EE, tid);
        }
        cpcommit();
        mma_tileT(Abuf[kt & 1], Kbuf[kt & 1], acc, wm, wn, g, tg);
        __syncthreads();
    }

    float lmax = -3.4e38f;
#pragma unroll
    for (int mi = 0; mi < 4; ++mi) {
        int r0 = t0 + wm * 64 + mi * 16 + g;
#pragma unroll
        for (int ni = 0; ni < 4; ++ni) {
            int c = s0 + wn * 32 + ni * 8 + 2 * tg;
#pragma unroll
            for (int q = 0; q < 4; ++q) {
                int r = r0 + (q >> 1) * 8;
                int cc = c + (q & 1);
                float v;
                if (cc <= r) {
                    v = acc[mi][ni][q] * 0.03125f;
                    lmax = fmaxf(lmax, v);
                } else {
                    v = -1e30f;
                }
                S[(size_t)r * TT + cc] = v;
            }
        }
    }

    __shared__ float red[256];
    red[tid] = lmax;
    __syncthreads();
    for (int st = 128; st > 0; st >>= 1) {
        if (tid < st) red[tid] = fmaxf(red[tid], red[tid + st]);
        __syncthreads();
    }
    if (tid == 0) atomicMax(&g_max_u[bz], f2mono(red[0]));
}

// ---------------------------------------------------------------------------
// exp(S - m) in place over causal blocks only + deterministic partial sums.
// grid = (NCB, BB); triangular decode of block index.
// ---------------------------------------------------------------------------
__global__ __launch_bounds__(256) void exp_kernel()
{
    const int bz = blockIdx.y;
    const int l = blockIdx.x;
    int tb = (int)((sqrtf(8.0f * l + 1.0f) - 1.0f) * 0.5f);
    while ((tb + 1) * (tb + 2) / 2 <= l) ++tb;
    while (tb * (tb + 1) / 2 > l) --tb;
    const int sb = l - tb * (tb + 1) / 2;
    const int t0 = tb * 128, s0 = sb * 128;

    const float m = mono2f(g_max_u[bz]);
    float* __restrict__ S = g_S + (size_t)bz * TT * TT;

    float lsum = 0.0f;
#pragma unroll
    for (int it = 0; it < 16; ++it) {
        int vidx = threadIdx.x + it * 256;
        int r = vidx >> 5, c = (vidx & 31) * 4;
        float4* p = reinterpret_cast<float4*>(&S[(size_t)(t0 + r) * TT + s0 + c]);
        float4 v = *p;
        v.x = expf(v.x - m);
        v.y = expf(v.y - m);
        v.z = expf(v.z - m);
        v.w = expf(v.w - m);
        *p = v;
        lsum += (v.x + v.y) + (v.z + v.w);
    }

    __shared__ float red[256];
    red[threadIdx.x] = lsum;
    __syncthreads();
    for (int st = 128; st > 0; st >>= 1) {
        if (threadIdx.x < st) red[threadIdx.x] += red[threadIdx.x + st];
        __syncthreads();
    }
    if (threadIdx.x == 0) g_psum[bz * NCB + l] = red[0];
}

__global__ __launch_bounds__(256) void reduce_kernel()
{
    const int bz = blockIdx.x;
    float s = 0.0f;
    for (int i = threadIdx.x; i < NCB; i += 256) s += g_psum[bz * NCB + i];
    __shared__ float red[256];
    red[threadIdx.x] = s;
    __syncthreads();
    for (int st = 128; st > 0; st >>= 1) {
        if (threadIdx.x < st) red[threadIdx.x] += red[threadIdx.x + st];
        __syncthreads();
    }
    if (threadIdx.x == 0) g_inv_sum[bz] = 1.0f / red[0];
}

// ---------------------------------------------------------------------------
// Output: O = (E @ V) * inv_sum; k-loop truncated at diagonal.
// ---------------------------------------------------------------------------
__global__ __launch_bounds__(256, 2) void out_kernel(float* __restrict__ O)
{
    const int bz = blockIdx.z;
    const int t0 = blockIdx.y * 128, n0 = blockIdx.x * 128;

    extern __shared__ __align__(16) float smem[];
    float* Abuf[2] = {smem, smem + A_WORDS};
    float* Bbuf[2] = {smem + 2 * A_WORDS, smem + 2 * A_WORDS + B_WORDS};
    uint32_t su = (uint32_t)__cvta_generic_to_shared(smem);
    uint32_t Au[2] = {su, su + A_WORDS * 4};
    uint32_t Bu[2] = {su + 2 * A_WORDS * 4, su + (2 * A_WORDS + B_WORDS) * 4};

    const int tid = threadIdx.x;
    const int warp = tid >> 5, lane = tid & 31;
    const int g = lane >> 2, tg = lane & 3;
    const int wm = warp >> 2, wn = warp & 3;

    const float* Eb = g_S + (size_t)bz * TT * TT + (size_t)t0 * TT;
    const float* Vb = g_V + (size_t)bz * TT * EE + n0;
    const float inv = g_inv_sum[bz];

    float acc[4][4][4] = {};

    fillA_async(Au[0], Eb, TT, tid);
    fillB_async(Bu[0], Vb, EE, tid);
    cpcommit();

    const int NK = (t0 + 128) / 32;
    for (int kt = 0; kt < NK; ++kt) {
        cpwait0();
        __syncthreads();
        if (kt + 1 < NK) {
            int k0 = (kt + 1) * 32;
            fillA_async(Au[(kt + 1) & 1], Eb + k0, TT, tid);
            fillB_async(Bu[(kt + 1) & 1], Vb + (size_t)k0 * EE, EE, tid);
        }
        cpcommit();
        mma_tileB(Abuf[kt & 1], Bbuf[kt & 1], acc, wm, wn, g, tg);
        __syncthreads();
    }

#pragma unroll
    for (int mi = 0; mi < 4; ++mi) {
        int r0 = t0 + wm * 64 + mi * 16 + g;
#pragma unroll
        for (int ni = 0; ni < 4; ++ni) {
            int c = n0 + wn * 32 + ni * 8 + 2 * tg;
            float2 v0 = make_float2(acc[mi][ni][0] * inv, acc[mi][ni][1] * inv);
            float2 v1 = make_float2(acc[mi][ni][2] * inv, acc[mi][ni][3] * inv);
            *reinterpret_cast<float2*>(&O[((size_t)bz * TT + r0) * EE + c]) = v0;
            *reinterpret_cast<float2*>(&O[((size_t)bz * TT + r0 + 8) * EE + c]) = v1;
        }
    }
}

// ---------------------------------------------------------------------------
extern "C" void kernel_launch(void* const* d_in, const int* in_sizes, int n_in,
                              void* d_out, int out_size)
{
    const float* x  = (const float*)d_in[0];
    const float* Wq = (const float*)d_in[1];
    const float* bq = (const float*)d_in[2];
    const float* Wk = (const float*)d_in[3];
    const float* bk = (const float*)d_in[4];
    const float* Wv = (const float*)d_in[5];
    const float* bv = (const float*)d_in[6];
    float* out = (float*)d_out;

    static bool attr_done = false;
    if (!attr_done) {
        cudaFuncSetAttribute(proj_kernel,
            cudaFuncAttributeMaxDynamicSharedMemorySize, PROJ_SMEM_BYTES);
        cudaFuncSetAttribute(scores_kernel,
            cudaFuncAttributeMaxDynamicSharedMemorySize, SCORES_SMEM_BYTES);
        cudaFuncSetAttribute(out_kernel,
            cudaFuncAttributeMaxDynamicSharedMemorySize, PROJ_SMEM_BYTES);
        attr_done = true;
    }

    init_kernel<<<1, 32>>>();

    dim3 pgrid(EE / 128, (BB * TT) / 128);
    proj_kernel<<<pgrid, 256, PROJ_SMEM_BYTES>>>(x, Wq, bq, 0);
    proj_kernel<<<pgrid, 256, PROJ_SMEM_BYTES>>>(x, Wk, bk, 1);
    proj_kernel<<<pgrid, 256, PROJ_SMEM_BYTES>>>(x, Wv, bv, 2);

    dim3 sgrid(TT / 128, TT / 128, BB);
    scores_kernel<<<sgrid, 256, SCORES_SMEM_BYTES>>>();

    exp_kernel<<<dim3(NCB, BB), 256>>>();
    reduce_kernel<<<BB, 256>>>();

    dim3 ogrid(EE / 128, TT / 128, BB);
    out_kernel<<<ogrid, 256, PROJ_SMEM_BYTES>>>(out);
}